// round 16
// baseline (speedup 1.0000x reference)
#include <cuda_runtime.h>

#define NATOMS   1500
#define NODE_DIM 128
#define HIDDEN   64
#define MUL1E    64
#define HID1E    32
#define NUM_BASIS 20
#define T        16      // edge tile side
#define NT       94      // ceil(1500/16)
#define ROWF     13500   // floats per output row: 1500*9
#define BSTRIDE  148     // padded row stride for transposed buffer (floats)

// Per-node packed data: a[3], b[3], coord[3], pad[3]  (48B = 3 x float4)
__device__ __align__(16) float g_node[NATOMS * 12];

__device__ __forceinline__ float silu_f(float d) {
    return d / (1.f + __expf(-d));
}

// One block = one node, 2 warps:
//   warp 0: scalar MLPs (lane<16: role i, lane>=16: role j; 4 hidden/lane)
//   warp 1: spherical MLPs (lane<16: role i, lane>=16: role j; 2 hidden/lane)
__global__ __launch_bounds__(64)
void node_kernel(
    const float* __restrict__ xs,   const float* __restrict__ xsph,
    const float* __restrict__ coord,
    const float* __restrict__ Wsi1, const float* __restrict__ Wsi2,
    const float* __restrict__ Wsj1, const float* __restrict__ Wsj2,
    const float* __restrict__ Wpi1, const float* __restrict__ Wpi2,
    const float* __restrict__ Wpj1, const float* __restrict__ Wpj2)
{
    int n = blockIdx.x;
    int t = threadIdx.x;
    int lane = t & 31;
    int w = t >> 5;

    __shared__ __align__(16) float4 sx4[NODE_DIM / 4];   // x features
    __shared__ __align__(16) float4 sv4[MUL1E];          // 1e vectors (v0,v1,v2,0)
    __shared__ float sS[2];          // scalar role sums
    __shared__ float sO[2][3];       // spherical role sums

    if (w == 0) {
        // ---- scalar MLPs ----
        sx4[lane] = ((const float4*)(xs + (size_t)n * NODE_DIM))[lane];
        __syncwarp();

        int half = lane >> 4;                 // 0: role i, 1: role j
        int hb = (lane & 15) * 4;
        const float* W1 = half ? Wsj1 : Wsi1;
        const float* W2 = half ? Wsj2 : Wsi2;
        const float* xf = (const float*)sx4;
        float a0 = 0.f, a1 = 0.f, a2 = 0.f, a3 = 0.f;
        #pragma unroll 8
        for (int f = 0; f < NODE_DIM; f++) {
            float x = xf[f];                              // LDS broadcast
            float4 wv = *(const float4*)(W1 + f * HIDDEN + hb);  // LDG.128
            a0 += x * wv.x; a1 += x * wv.y; a2 += x * wv.z; a3 += x * wv.w;
        }
        float4 w2v = *(const float4*)(W2 + hb);
        float v = silu_f(a0) * w2v.x + silu_f(a1) * w2v.y
                + silu_f(a2) * w2v.z + silu_f(a3) * w2v.w;
        #pragma unroll
        for (int off = 1; off < 16; off <<= 1) v += __shfl_xor_sync(0xffffffffu, v, off);
        if ((lane & 15) == 0) sS[half] = v;
    } else {
        // ---- spherical MLPs ----
        for (int m = lane; m < MUL1E; m += 32) {
            const float* vp = xsph + (size_t)n * 480 + 128 + 3 * m;
            sv4[m] = make_float4(vp[0], vp[1], vp[2], 0.f);
        }
        __syncwarp();

        int half = lane >> 4;
        int hb = (lane & 15) * 2;
        const float* P1 = half ? Wpj1 : Wpi1;
        const float* P2 = half ? Wpj2 : Wpi2;
        float h00 = 0.f, h01 = 0.f, h02 = 0.f;
        float h10 = 0.f, h11 = 0.f, h12 = 0.f;
        #pragma unroll 8
        for (int m = 0; m < MUL1E; m++) {
            float4 vv = sv4[m];                           // LDS.128 broadcast
            float2 pw = *(const float2*)(P1 + m * HID1E + hb);   // LDG.64
            h00 += vv.x * pw.x; h01 += vv.y * pw.x; h02 += vv.z * pw.x;
            h10 += vv.x * pw.y; h11 += vv.y * pw.y; h12 += vv.z * pw.y;
        }
        h00 *= 0.125f; h01 *= 0.125f; h02 *= 0.125f;      // / sqrt(64)
        h10 *= 0.125f; h11 *= 0.125f; h12 *= 0.125f;
        float2 p2v = *(const float2*)(P2 + hb);
        float n0 = sqrtf(h00 * h00 + h01 * h01 + h02 * h02);
        float n1 = sqrtf(h10 * h10 + h11 * h11 + h12 * h12);
        float wa = p2v.x / (1.f + __expf(-n0));           // W2 * sigmoid(|h|)
        float wb = p2v.y / (1.f + __expf(-n1));
        float o0 = h00 * wa + h10 * wb;
        float o1 = h01 * wa + h11 * wb;
        float o2 = h02 * wa + h12 * wb;
        #pragma unroll
        for (int off = 1; off < 16; off <<= 1) {
            o0 += __shfl_xor_sync(0xffffffffu, o0, off);
            o1 += __shfl_xor_sync(0xffffffffu, o1, off);
            o2 += __shfl_xor_sync(0xffffffffu, o2, off);
        }
        if ((lane & 15) == 0) { sO[half][0] = o0; sO[half][1] = o1; sO[half][2] = o2; }
    }
    __syncthreads();

    if (t == 0) {
        const float inv32 = 0.17677669529663689f;         // 1/sqrt(32)
        float fa = (1.f + sS[0]) * inv32;
        float fb = (1.f + sS[1]) * inv32;
        float cx = coord[n * 3 + 0], cy = coord[n * 3 + 1], cz = coord[n * 3 + 2];
        float4* gp = (float4*)(g_node + n * 12);
        // e3nn (y,z,x) -> (x,y,z) permutation [2,0,1], fold in gate (1+s)
        gp[0] = make_float4(sO[0][2] * fa, sO[0][0] * fa, sO[0][1] * fa, sO[1][2] * fb);
        gp[1] = make_float4(sO[1][0] * fb, sO[1][1] * fb, cx, cy);
        gp[2] = make_float4(cz, 0.f, 0.f, 0.f);
    }
}

// Symmetric 16x16 tiles over the upper triangle; dual-layout smem staging;
// fc via 9-term windowed expf sum (measured best).
__global__ __launch_bounds__(256)
void edge_kernel(const float* __restrict__ Wrbf, float* __restrict__ out)
{
    int b = blockIdx.x;
    // triangular decode (once per block)
    int ti = (int)((2.f * NT + 1.f - sqrtf((2.f * NT + 1.f) * (2.f * NT + 1.f) - 8.f * (float)b)) * 0.5f);
    if (ti < 0) ti = 0; if (ti > NT - 1) ti = NT - 1;
    while (ti * NT - ti * (ti - 1) / 2 > b) ti--;
    while ((ti + 1) * NT - (ti + 1) * ti / 2 <= b) ti++;
    int tj = ti + (b - (ti * NT - ti * (ti - 1) / 2));

    int t  = threadIdx.x;
    int tx = t & 15;        // j within tile
    int ty = t >> 4;        // i within tile

    __shared__ __align__(16) float sbufA[T * T * 9];      // [ii][jj*9+c]
    __shared__ __align__(16) float sbufB[T * BSTRIDE];    // [jj][ii*9+cT]
    __shared__ __align__(16) float4 gi4[T][3];
    __shared__ __align__(16) float4 gj4[T][3];
    __shared__ float sWp[33];   // zero-padded: sWp[k+4] = W[k]

    if (t < 33) {
        int k = t - 4;
        sWp[t] = (k >= 0 && k < NUM_BASIS) ? Wrbf[k] : 0.f;
    }
    if (t >= 64 && t < 112) {
        int u = t - 64;
        int n = ti * T + u / 3;
        ((float4*)gi4)[u] = (n < NATOMS) ? ((const float4*)g_node)[n * 3 + u % 3]
                                         : make_float4(0.f, 0.f, 0.f, 0.f);
    }
    if (t >= 128 && t < 176) {
        int u = t - 128;
        int n = tj * T + u / 3;
        ((float4*)gj4)[u] = (n < NATOMS) ? ((const float4*)g_node)[n * 3 + u % 3]
                                         : make_float4(0.f, 0.f, 0.f, 0.f);
    }
    __syncthreads();

    int vi = NATOMS - ti * T; if (vi > T) vi = T;
    int vj = NATOMS - tj * T; if (vj > T) vj = T;
    bool offdiag = (ti != tj);

    if (ty < vi && tx < vj) {
        float4 i0 = gi4[ty][0], i1 = gi4[ty][1], i2 = gi4[ty][2];
        float4 j0 = gj4[tx][0], j1 = gj4[tx][1], j2 = gj4[tx][2];

        float dx = i1.z - j1.z, dy = i1.w - j1.w, dz = i2.x - j2.x;
        float d = sqrtf(dx * dx + dy * dy + dz * dz);

        const float delta = 5.0f / 19.0f;
        const float coeff = -0.5f / (delta * delta);
        int k0 = __float2int_rn(d * (19.0f / 5.0f));
        int k0c = min(k0, 24);
        float u0 = d - (float)(k0c - 4) * delta;   // u for kk=0
        float fc = 0.f;
        #pragma unroll
        for (int kk = 0; kk < 9; kk++) {
            float u = u0 - (float)kk * delta;
            fc += sWp[k0c + kk] * __expf(coeff * u * u);
        }
        float h = 0.5f * fc;

        float ai0 = i0.x * h, ai1 = i0.y * h, ai2 = i0.z * h;
        float bi0 = i0.w * h, bi1 = i1.x * h, bi2 = i1.y * h;
        float aj0 = j0.x, aj1 = j0.y, aj2 = j0.z;
        float bj0 = j0.w, bj1 = j1.x, bj2 = j1.y;

        float m00 = ai0 * bj0 + bi0 * aj0;
        float m01 = ai0 * bj1 + bi0 * aj1;
        float m02 = ai0 * bj2 + bi0 * aj2;
        float m10 = ai1 * bj0 + bi1 * aj0;
        float m11 = ai1 * bj1 + bi1 * aj1;
        float m12 = ai1 * bj2 + bi1 * aj2;
        float m20 = ai2 * bj0 + bi2 * aj0;
        float m21 = ai2 * bj1 + bi2 * aj1;
        float m22 = ai2 * bj2 + bi2 * aj2;

        float* a = sbufA + ty * (T * 9) + tx * 9;
        a[0] = m00; a[1] = m01; a[2] = m02;
        a[3] = m10; a[4] = m11; a[5] = m12;
        a[6] = m20; a[7] = m21; a[8] = m22;

        if (offdiag) {
            float* bq = sbufB + tx * BSTRIDE + ty * 9;
            bq[0] = m00; bq[1] = m10; bq[2] = m20;
            bq[3] = m01; bq[4] = m11; bq[5] = m21;
            bq[6] = m02; bq[7] = m12; bq[8] = m22;
        }
    }
    __syncthreads();

    if (ty < vi) {
        int w4 = (vj * 9) >> 2;
        const float4* src = (const float4*)(sbufA + ty * (T * 9));
        float4* dst = (float4*)(out + (size_t)(ti * T + ty) * ROWF + (size_t)tj * T * 9);
        #pragma unroll
        for (int c = tx; c < 36; c += 16)
            if (c < w4) dst[c] = src[c];
    }

    if (offdiag && ty < vj) {
        int w4 = (vi * 9) >> 2;
        const float4* src = (const float4*)(sbufB + ty * BSTRIDE);
        float4* dst = (float4*)(out + (size_t)(tj * T + ty) * ROWF + (size_t)ti * T * 9);
        #pragma unroll
        for (int c = tx; c < 36; c += 16)
            if (c < w4) dst[c] = src[c];
    }
}

extern "C" void kernel_launch(void* const* d_in, const int* in_sizes, int n_in,
                              void* d_out, int out_size)
{
    const float* xs    = (const float*)d_in[0];
    const float* xsph  = (const float*)d_in[1];
    const float* coord = (const float*)d_in[2];
    // d_in[3] = fc_edge_index (int32, full graph i-major) — structure fixed, unused
    const float* Wsi1 = (const float*)d_in[4];
    const float* Wsi2 = (const float*)d_in[5];
    const float* Wsj1 = (const float*)d_in[6];
    const float* Wsj2 = (const float*)d_in[7];
    const float* Wpi1 = (const float*)d_in[8];
    const float* Wpi2 = (const float*)d_in[9];
    const float* Wpj1 = (const float*)d_in[10];
    const float* Wpj2 = (const float*)d_in[11];
    const float* Wrbf = (const float*)d_in[12];
    float* out = (float*)d_out;

    node_kernel<<<NATOMS, 64>>>(xs, xsph, coord,
                                Wsi1, Wsi2, Wsj1, Wsj2,
                                Wpi1, Wpi2, Wpj1, Wpj2);

    int nblocks = NT * (NT + 1) / 2;   // 4465 upper-triangle tiles
    edge_kernel<<<nblocks, 256>>>(Wrbf, out);
}